// round 3
// baseline (speedup 1.0000x reference)
#include <cuda_runtime.h>
#include <cuda_bf16.h>
#include <math.h>

// Problem constants
#define BB   2
#define SS   2048
#define DD   1024
#define HH   16
#define DK   64
#define HALF 64

// ---------------- scratch (device globals; no runtime allocation) ----------
__device__ float g_q[BB*HH*SS*DK];   // [B,H,S,DK]
__device__ float g_k[BB*HH*SS*DK];
__device__ float g_v[BB*HH*SS*DK];
__device__ float g_x[BB*SS*DD];      // [B,S,D] attention output (pre out-proj)

// ---------------- helpers ----------------------------------------------------
__device__ __forceinline__ unsigned cvta_sh(const void* p) {
    return (unsigned)__cvta_generic_to_shared(p);
}
__device__ __forceinline__ unsigned cvt_tf32(float x) {
    unsigned r; asm("cvt.rna.tf32.f32 %0, %1;" : "=r"(r) : "f"(x)); return r;
}
#define CP_ASYNC16(saddr, gaddr) \
    asm volatile("cp.async.cg.shared.global [%0], [%1], 16;\n" :: "r"(saddr), "l"(gaddr))
#define CP_COMMIT() asm volatile("cp.async.commit_group;\n" ::)
#define CP_WAIT(N)  asm volatile("cp.async.wait_group %0;\n" :: "n"(N))

// ---------------- TF32 tensor-core GEMM --------------------------------------
// C[M,N] = A[M,K=1024] @ W[K,N=1024] + bias ; 128x128 block, BK=32,
// 8 warps of 64x32, m16n8k8 tf32 mma. cp.async double-buffered.
#define AS_STRIDE 36     // 128 x 36 floats per stage (conflict-free frag loads)
#define BS_STRIDE 136    // 32 x 136 floats per stage
#define AS_STAGE  (128 * AS_STRIDE)
#define BS_STAGE  (32 * BS_STRIDE)
#define SMEM_GEMM ((2 * (AS_STAGE + BS_STAGE)) * 4)   // 71680 B

__device__ __forceinline__ void gemm_load_stage(
    const float* __restrict__ A, const float* __restrict__ W,
    float* As, float* Bs, int stage, int k0, int m0, int n0, int tid)
{
    float* Ad = As + stage * AS_STAGE;
    float* Bd = Bs + stage * BS_STAGE;
    #pragma unroll
    for (int i = 0; i < 4; i++) {
        int f = tid + i * 256;          // 1024 float4 for A: 128 rows x 8 f4
        int r = f >> 3, c4 = f & 7;
        CP_ASYNC16(cvta_sh(&Ad[r * AS_STRIDE + c4 * 4]),
                   &A[(size_t)(m0 + r) * DD + k0 + c4 * 4]);
    }
    #pragma unroll
    for (int i = 0; i < 4; i++) {
        int f = tid + i * 256;          // 1024 float4 for B: 32 rows x 32 f4
        int r = f >> 5, c4 = f & 31;
        CP_ASYNC16(cvta_sh(&Bd[r * BS_STRIDE + c4 * 4]),
                   &W[(size_t)(k0 + r) * DD + n0 + c4 * 4]);
    }
    CP_COMMIT();
}

__device__ __forceinline__ void gemm_tf32(const float* __restrict__ A,
                                          const float* __restrict__ W,
                                          const float* __restrict__ bias,
                                          float* __restrict__ C,
                                          bool permuted)
{
    extern __shared__ float sm[];
    float* As = sm;
    float* Bs = sm + 2 * AS_STAGE;

    const int tid  = threadIdx.x;
    const int lane = tid & 31;
    const int wid  = tid >> 5;
    const int wm   = wid >> 2;           // 0..1
    const int wn   = wid & 3;            // 0..3
    const int m0   = blockIdx.y * 128;
    const int n0   = blockIdx.x * 128;
    const int g    = lane >> 2;          // 0..7
    const int kq   = lane & 3;           // 0..3

    float acc[4][4][4];
    #pragma unroll
    for (int i = 0; i < 4; i++)
        #pragma unroll
        for (int j = 0; j < 4; j++)
            #pragma unroll
            for (int e = 0; e < 4; e++) acc[i][j][e] = 0.f;

    gemm_load_stage(A, W, As, Bs, 0, 0, m0, n0, tid);

    #pragma unroll 1
    for (int t = 0; t < DD / 32; ++t) {
        if (t + 1 < DD / 32) {
            gemm_load_stage(A, W, As, Bs, (t + 1) & 1, (t + 1) * 32, m0, n0, tid);
            CP_WAIT(1);
        } else {
            CP_WAIT(0);
        }
        __syncthreads();

        const float* Ab = As + (t & 1) * AS_STAGE;
        const float* Bb = Bs + (t & 1) * BS_STAGE;

        #pragma unroll
        for (int kk = 0; kk < 4; ++kk) {
            const int kr = kk * 8 + kq;
            unsigned a[4][4], b[4][2];
            #pragma unroll
            for (int mf = 0; mf < 4; ++mf) {
                int m = wm * 64 + mf * 16 + g;
                a[mf][0] = cvt_tf32(Ab[m * AS_STRIDE + kr]);
                a[mf][1] = cvt_tf32(Ab[(m + 8) * AS_STRIDE + kr]);
                a[mf][2] = cvt_tf32(Ab[m * AS_STRIDE + kr + 4]);
                a[mf][3] = cvt_tf32(Ab[(m + 8) * AS_STRIDE + kr + 4]);
            }
            #pragma unroll
            for (int nf = 0; nf < 4; ++nf) {
                int n = wn * 32 + nf * 8 + g;
                b[nf][0] = cvt_tf32(Bb[kr * BS_STRIDE + n]);
                b[nf][1] = cvt_tf32(Bb[(kr + 4) * BS_STRIDE + n]);
            }
            #pragma unroll
            for (int mf = 0; mf < 4; ++mf)
                #pragma unroll
                for (int nf = 0; nf < 4; ++nf) {
                    asm volatile(
                        "mma.sync.aligned.m16n8k8.row.col.f32.tf32.tf32.f32 "
                        "{%0,%1,%2,%3}, {%4,%5,%6,%7}, {%8,%9}, {%0,%1,%2,%3};"
                        : "+f"(acc[mf][nf][0]), "+f"(acc[mf][nf][1]),
                          "+f"(acc[mf][nf][2]), "+f"(acc[mf][nf][3])
                        : "r"(a[mf][0]), "r"(a[mf][1]), "r"(a[mf][2]), "r"(a[mf][3]),
                          "r"(b[nf][0]), "r"(b[nf][1]));
                }
        }
        __syncthreads();
    }

    // epilogue
    #pragma unroll
    for (int mf = 0; mf < 4; ++mf) {
        #pragma unroll
        for (int nf = 0; nf < 4; ++nf) {
            int m = m0 + wm * 64 + mf * 16 + g;
            int n = n0 + wn * 32 + nf * 8 + 2 * kq;
            float bn0 = bias[n], bn1 = bias[n + 1];
            #pragma unroll
            for (int half = 0; half < 2; ++half) {
                int mm = m + half * 8;
                float v0 = acc[mf][nf][half * 2 + 0] + bn0;
                float v1 = acc[mf][nf][half * 2 + 1] + bn1;
                int bb = mm >> 11, s = mm & 2047;
                if (permuted) {
                    int h = n >> 6, dk = n & 63;
                    float2* dst = reinterpret_cast<float2*>(
                        &C[((size_t)(bb * HH + h) * SS + s) * DK + dk]);
                    *dst = make_float2(v0, v1);
                } else {
                    float2* dst = reinterpret_cast<float2*>(&C[(size_t)mm * DD + n]);
                    *dst = make_float2(v0, v1);
                }
            }
        }
    }
}

__global__ __launch_bounds__(256, 2) void qkv_proj_kernel(
    const float* __restrict__ q, const float* __restrict__ k, const float* __restrict__ v,
    const float* __restrict__ Wq, const float* __restrict__ Wk, const float* __restrict__ Wv,
    const float* __restrict__ bq, const float* __restrict__ bk, const float* __restrict__ bv,
    float* __restrict__ zattn)
{
    int w = blockIdx.z;
    const float* A  = (w == 0) ? q  : (w == 1) ? k  : v;
    const float* W  = (w == 0) ? Wq : (w == 1) ? Wk : Wv;
    const float* bi = (w == 0) ? bq : (w == 1) ? bk : bv;
    float* C        = (w == 0) ? g_q : (w == 1) ? g_k : g_v;
    gemm_tf32(A, W, bi, C, true);

    // ---- zero-fill the attn matrix under the compute-bound GEMM ----
    // (DRAM was 5.4% busy; 537 MB of writes ride along nearly free)
    const size_t total4 = (size_t)BB * HH * SS * SS / 4;   // float4 count
    const int bid = blockIdx.x + blockIdx.y * 8 + blockIdx.z * 256;  // 0..767
    float4* dst = reinterpret_cast<float4*>(zattn);
    const float4 z = make_float4(0.f, 0.f, 0.f, 0.f);
    for (size_t i = (size_t)bid * 256 + threadIdx.x; i < total4; i += (size_t)768 * 256)
        dst[i] = z;
}

__global__ __launch_bounds__(256, 2) void out_proj_kernel(
    const float* __restrict__ Wo, const float* __restrict__ bo, float* __restrict__ out)
{
    gemm_tf32(g_x, Wo, bo, out, false);
}

// ---------------- banded attention ------------------------------------------
// smem: Qs 64x68, Ks 192x68, Vs 192x68, Ps 64x132
#define Q_STRIDE 68
#define K_STRIDE 68
#define V_STRIDE 68
#define P_STRIDE 132
#define SMEM_ATTN ((64*Q_STRIDE + 192*K_STRIDE + 192*V_STRIDE + 64*P_STRIDE) * 4)

__global__ __launch_bounds__(256) void attn_kernel(float* __restrict__ attn_out)
{
    extern __shared__ float sm[];
    float* Qs = sm;
    float* Ks = Qs + 64 * Q_STRIDE;
    float* Vs = Ks + 192 * K_STRIDE;
    float* Ps = Vs + 192 * V_STRIDE;

    const int tid = threadIdx.x;
    const int bh  = blockIdx.y;
    const int i0  = blockIdx.x * 64;
    const int b   = bh >> 4, h = bh & 15;

    const float* Qg = g_q + (size_t)bh * SS * DK;
    const float* Kg = g_k + (size_t)bh * SS * DK;
    const float* Vg = g_v + (size_t)bh * SS * DK;

    // ---- load Q (64x64) ----
    #pragma unroll
    for (int i = 0; i < 4; i++) {
        int f = tid + i * 256;
        int r = f >> 4, c = (f & 15) << 2;
        float4 v = *reinterpret_cast<const float4*>(&Qg[(size_t)(i0 + r) * DK + c]);
        *reinterpret_cast<float4*>(&Qs[r * Q_STRIDE + c]) = v;
    }
    // ---- load K,V (192x64), zero-fill out of range ----
    const int kg0 = i0 - HALF;
    #pragma unroll
    for (int i = 0; i < 12; i++) {
        int f = tid + i * 256;
        int r = f >> 4, c = (f & 15) << 2;
        int gr = kg0 + r;
        float4 kv = make_float4(0.f, 0.f, 0.f, 0.f);
        float4 vv = kv;
        if (gr >= 0 && gr < SS) {
            kv = *reinterpret_cast<const float4*>(&Kg[(size_t)gr * DK + c]);
            vv = *reinterpret_cast<const float4*>(&Vg[(size_t)gr * DK + c]);
        }
        *reinterpret_cast<float4*>(&Ks[r * K_STRIDE + c]) = kv;
        *reinterpret_cast<float4*>(&Vs[r * V_STRIDE + c]) = vv;
    }
    __syncthreads();

    // ---- scores + softmax: warp per 8 query rows, lanes split 129-key window
    const int warp = tid >> 5, lane = tid & 31;
    for (int r8 = 0; r8 < 8; ++r8) {
        const int il = warp * 8 + r8;
        const int qg = i0 + il;
        float acc[5];
        const float4* kr4[5];
        bool  val[5];
        #pragma unroll
        for (int gg = 0; gg < 5; ++gg) {
            int t = lane + 32 * gg;
            int j = qg - HALF + t;
            val[gg] = (t <= 128) && (j >= 0) && (j < SS);
            kr4[gg] = reinterpret_cast<const float4*>(&Ks[(val[gg] ? (il + t) : 0) * K_STRIDE]);
            acc[gg] = 0.f;
        }
        const float4* qr4 = reinterpret_cast<const float4*>(&Qs[il * Q_STRIDE]);
        #pragma unroll
        for (int d4 = 0; d4 < DK / 4; ++d4) {
            float4 qv = qr4[d4];
            #pragma unroll
            for (int gg = 0; gg < 5; ++gg) {
                float4 kv = kr4[gg][d4];
                acc[gg] += qv.x * kv.x + qv.y * kv.y + qv.z * kv.z + qv.w * kv.w;
            }
        }
        float mx = -INFINITY;
        #pragma unroll
        for (int gg = 0; gg < 5; ++gg) {
            acc[gg] = val[gg] ? acc[gg] * 0.125f : -INFINITY;
            mx = fmaxf(mx, acc[gg]);
        }
        #pragma unroll
        for (int o = 16; o > 0; o >>= 1) mx = fmaxf(mx, __shfl_xor_sync(0xffffffffu, mx, o));
        float sum = 0.f;
        #pragma unroll
        for (int gg = 0; gg < 5; ++gg) {
            float e = __expf(acc[gg] - mx);
            acc[gg] = e; sum += e;
        }
        #pragma unroll
        for (int o = 16; o > 0; o >>= 1) sum += __shfl_xor_sync(0xffffffffu, sum, o);
        float inv = 1.0f / sum;
        #pragma unroll
        for (int gg = 0; gg < 5; ++gg) {
            int t = lane + 32 * gg;
            if (t <= 128) Ps[il * P_STRIDE + t] = acc[gg] * inv;
        }
    }
    __syncthreads();

    // ---- P @ V : thread owns (row, 16 dk) ----
    {
        const int il  = tid >> 2;
        const int dk0 = (tid & 3) << 4;
        const int qg  = i0 + il;
        int t0 = (qg >= HALF) ? 0 : (HALF - qg);
        int t1 = 128;
        int tmax = (SS - 1 - qg) + HALF;
        if (tmax < t1) t1 = tmax;

        float acc[16];
        #pragma unroll
        for (int e = 0; e < 16; e++) acc[e] = 0.f;
        for (int t = t0; t <= t1; ++t) {
            float p = Ps[il * P_STRIDE + t];
            const float* vr = &Vs[(il + t) * V_STRIDE + dk0];
            #pragma unroll
            for (int e4 = 0; e4 < 4; e4++) {
                float4 v = *reinterpret_cast<const float4*>(&vr[e4 * 4]);
                acc[e4*4+0] += p * v.x; acc[e4*4+1] += p * v.y;
                acc[e4*4+2] += p * v.z; acc[e4*4+3] += p * v.w;
            }
        }
        float* xo = &g_x[((size_t)b * SS + qg) * DD + h * DK + dk0];
        #pragma unroll
        for (int e4 = 0; e4 < 4; e4++)
            *reinterpret_cast<float4*>(&xo[e4 * 4]) =
                make_float4(acc[e4*4], acc[e4*4+1], acc[e4*4+2], acc[e4*4+3]);
    }

    // ---- write band of attn matrix (rest zero-filled by qkv_proj) ----
    for (int idx = tid; idx < 64 * 129; idx += 256) {
        int r = idx / 129;
        int t = idx - r * 129;
        int qg = i0 + r;
        int j  = qg - HALF + t;
        if (j >= 0 && j < SS)
            attn_out[((size_t)bh * SS + qg) * SS + j] = Ps[r * P_STRIDE + t];
    }
}

// ---------------- launch -----------------------------------------------------
extern "C" void kernel_launch(void* const* d_in, const int* in_sizes, int n_in,
                              void* d_out, int out_size)
{
    const float* query = (const float*)d_in[0];
    const float* key   = (const float*)d_in[1];
    const float* value = (const float*)d_in[2];
    const float* Wq    = (const float*)d_in[3];
    const float* bq    = (const float*)d_in[4];
    const float* Wk    = (const float*)d_in[5];
    const float* bk    = (const float*)d_in[6];
    const float* Wv    = (const float*)d_in[7];
    const float* bv    = (const float*)d_in[8];
    const float* Wo    = (const float*)d_in[9];
    const float* bo    = (const float*)d_in[10];

    float* out  = (float*)d_out;
    float* attn = out + (size_t)BB * SS * DD;

    cudaFuncSetAttribute(qkv_proj_kernel, cudaFuncAttributeMaxDynamicSharedMemorySize, SMEM_GEMM);
    cudaFuncSetAttribute(out_proj_kernel, cudaFuncAttributeMaxDynamicSharedMemorySize, SMEM_GEMM);
    cudaFuncSetAttribute(attn_kernel,     cudaFuncAttributeMaxDynamicSharedMemorySize, SMEM_ATTN);

    // Q/K/V projections (tensor-core TF32) + attn-matrix zero-fill
    qkv_proj_kernel<<<dim3(8, 32, 3), 256, SMEM_GEMM>>>(query, key, value,
                                                        Wq, Wk, Wv, bq, bk, bv, attn);

    // banded attention (writes only the band; zeros already laid down)
    attn_kernel<<<dim3(SS / 64, BB * HH), 256, SMEM_ATTN>>>(attn);

    // output projection
    out_proj_kernel<<<dim3(8, 32), 256, SMEM_GEMM>>>(Wo, bo, out);
}

// round 4
// speedup vs baseline: 1.5637x; 1.5637x over previous
#include <cuda_runtime.h>
#include <cuda_bf16.h>
#include <math.h>

// Problem constants
#define BB   2
#define SS   2048
#define DD   1024
#define HH   16
#define DK   64
#define HALF 64

// ---------------- scratch (device globals; no runtime allocation) ----------
__device__ float g_q[BB*HH*SS*DK];   // [B,H,S,DK]
__device__ float g_k[BB*HH*SS*DK];
__device__ float g_v[BB*HH*SS*DK];
__device__ float g_x[BB*SS*DD];      // [B,S,D] attention output (pre out-proj)

// ---------------- helpers ----------------------------------------------------
__device__ __forceinline__ unsigned cvta_sh(const void* p) {
    return (unsigned)__cvta_generic_to_shared(p);
}
__device__ __forceinline__ unsigned cvt_tf32(float x) {
    unsigned r; asm("cvt.rna.tf32.f32 %0, %1;" : "=r"(r) : "f"(x)); return r;
}
#define CP_ASYNC16(saddr, gaddr) \
    asm volatile("cp.async.cg.shared.global [%0], [%1], 16;\n" :: "r"(saddr), "l"(gaddr))
#define CP_COMMIT() asm volatile("cp.async.commit_group;\n" ::)
#define CP_WAIT(N)  asm volatile("cp.async.wait_group %0;\n" :: "n"(N))

#define MMA_TF32(ac, a0,a1,a2,a3, b0,b1) \
    asm volatile( \
        "mma.sync.aligned.m16n8k8.row.col.f32.tf32.tf32.f32 " \
        "{%0,%1,%2,%3}, {%4,%5,%6,%7}, {%8,%9}, {%0,%1,%2,%3};" \
        : "+f"((ac)[0]), "+f"((ac)[1]), "+f"((ac)[2]), "+f"((ac)[3]) \
        : "r"(a0), "r"(a1), "r"(a2), "r"(a3), "r"(b0), "r"(b1))

// ---------------- TF32 tensor-core GEMM --------------------------------------
#define AS_STRIDE 36
#define BS_STRIDE 136
#define AS_STAGE  (128 * AS_STRIDE)
#define BS_STAGE  (32 * BS_STRIDE)
#define SMEM_GEMM ((2 * (AS_STAGE + BS_STAGE)) * 4)   // 71680 B

#define FILL_TOTAL4 ((size_t)BB * HH * SS * SS / 4)    // 33554432 float4
#define FILL_THREADS ((size_t)768 * 256)

__device__ __forceinline__ void gemm_load_stage(
    const float* __restrict__ A, const float* __restrict__ W,
    float* As, float* Bs, int stage, int k0, int m0, int n0, int tid)
{
    float* Ad = As + stage * AS_STAGE;
    float* Bd = Bs + stage * BS_STAGE;
    #pragma unroll
    for (int i = 0; i < 4; i++) {
        int f = tid + i * 256;
        int r = f >> 3, c4 = f & 7;
        CP_ASYNC16(cvta_sh(&Ad[r * AS_STRIDE + c4 * 4]),
                   &A[(size_t)(m0 + r) * DD + k0 + c4 * 4]);
    }
    #pragma unroll
    for (int i = 0; i < 4; i++) {
        int f = tid + i * 256;
        int r = f >> 5, c4 = f & 31;
        CP_ASYNC16(cvta_sh(&Bd[r * BS_STRIDE + c4 * 4]),
                   &W[(size_t)(k0 + r) * DD + n0 + c4 * 4]);
    }
    CP_COMMIT();
}

template <bool FILL>
__device__ __forceinline__ void gemm_tf32(const float* __restrict__ A,
                                          const float* __restrict__ W,
                                          const float* __restrict__ bias,
                                          float* __restrict__ C,
                                          bool permuted,
                                          float4* __restrict__ zdst,
                                          size_t gtid)
{
    extern __shared__ float sm[];
    float* As = sm;
    float* Bs = sm + 2 * AS_STAGE;

    const int tid  = threadIdx.x;
    const int lane = tid & 31;
    const int wid  = tid >> 5;
    const int wm   = wid >> 2;
    const int wn   = wid & 3;
    const int m0   = blockIdx.y * 128;
    const int n0   = blockIdx.x * 128;
    const int g    = lane >> 2;
    const int kq   = lane & 3;

    float acc[4][4][4];
    #pragma unroll
    for (int i = 0; i < 4; i++)
        #pragma unroll
        for (int j = 0; j < 4; j++)
            #pragma unroll
            for (int e = 0; e < 4; e++) acc[i][j][e] = 0.f;

    gemm_load_stage(A, W, As, Bs, 0, 0, m0, n0, tid);

    const float4 z4 = make_float4(0.f, 0.f, 0.f, 0.f);

    #pragma unroll 1
    for (int t = 0; t < DD / 32; ++t) {
        if (t + 1 < DD / 32) {
            gemm_load_stage(A, W, As, Bs, (t + 1) & 1, (t + 1) * 32, m0, n0, tid);
            CP_WAIT(1);
        } else {
            CP_WAIT(0);
        }
        __syncthreads();

        // interleaved zero-fill of the attn matrix: rides the idle DRAM
        // write bandwidth underneath the tensor-pipe-bound mainloop.
        if (FILL) {
            #pragma unroll
            for (int u = 0; u < 6; ++u) {
                size_t idx = (size_t)(t * 6 + u) * FILL_THREADS + gtid;
                if (idx < FILL_TOTAL4) zdst[idx] = z4;
            }
        }

        const float* Ab = As + (t & 1) * AS_STAGE;
        const float* Bb = Bs + (t & 1) * BS_STAGE;

        #pragma unroll
        for (int kk = 0; kk < 4; ++kk) {
            const int kr = kk * 8 + kq;
            unsigned a[4][4], b[4][2];
            #pragma unroll
            for (int mf = 0; mf < 4; ++mf) {
                int m = wm * 64 + mf * 16 + g;
                a[mf][0] = cvt_tf32(Ab[m * AS_STRIDE + kr]);
                a[mf][1] = cvt_tf32(Ab[(m + 8) * AS_STRIDE + kr]);
                a[mf][2] = cvt_tf32(Ab[m * AS_STRIDE + kr + 4]);
                a[mf][3] = cvt_tf32(Ab[(m + 8) * AS_STRIDE + kr + 4]);
            }
            #pragma unroll
            for (int nf = 0; nf < 4; ++nf) {
                int n = wn * 32 + nf * 8 + g;
                b[nf][0] = cvt_tf32(Bb[kr * BS_STRIDE + n]);
                b[nf][1] = cvt_tf32(Bb[(kr + 4) * BS_STRIDE + n]);
            }
            #pragma unroll
            for (int mf = 0; mf < 4; ++mf)
                #pragma unroll
                for (int nf = 0; nf < 4; ++nf)
                    MMA_TF32(acc[mf][nf], a[mf][0], a[mf][1], a[mf][2], a[mf][3],
                             b[nf][0], b[nf][1]);
        }
        __syncthreads();
    }

    // epilogue
    #pragma unroll
    for (int mf = 0; mf < 4; ++mf) {
        #pragma unroll
        for (int nf = 0; nf < 4; ++nf) {
            int m = m0 + wm * 64 + mf * 16 + g;
            int n = n0 + wn * 32 + nf * 8 + 2 * kq;
            float bn0 = bias[n], bn1 = bias[n + 1];
            #pragma unroll
            for (int half = 0; half < 2; ++half) {
                int mm = m + half * 8;
                float v0 = acc[mf][nf][half * 2 + 0] + bn0;
                float v1 = acc[mf][nf][half * 2 + 1] + bn1;
                int bb = mm >> 11, s = mm & 2047;
                if (permuted) {
                    int h = n >> 6, dk = n & 63;
                    float2* dst = reinterpret_cast<float2*>(
                        &C[((size_t)(bb * HH + h) * SS + s) * DK + dk]);
                    *dst = make_float2(v0, v1);
                } else {
                    float2* dst = reinterpret_cast<float2*>(&C[(size_t)mm * DD + n]);
                    *dst = make_float2(v0, v1);
                }
            }
        }
    }
}

__global__ __launch_bounds__(256, 2) void qkv_proj_kernel(
    const float* __restrict__ q, const float* __restrict__ k, const float* __restrict__ v,
    const float* __restrict__ Wq, const float* __restrict__ Wk, const float* __restrict__ Wv,
    const float* __restrict__ bq, const float* __restrict__ bk, const float* __restrict__ bv,
    float* __restrict__ zattn)
{
    int w = blockIdx.z;
    const float* A  = (w == 0) ? q  : (w == 1) ? k  : v;
    const float* W  = (w == 0) ? Wq : (w == 1) ? Wk : Wv;
    const float* bi = (w == 0) ? bq : (w == 1) ? bk : bv;
    float* C        = (w == 0) ? g_q : (w == 1) ? g_k : g_v;
    const int bid   = blockIdx.x + blockIdx.y * 8 + blockIdx.z * 256;   // 0..767
    size_t gtid     = (size_t)bid * 256 + threadIdx.x;
    gemm_tf32<true>(A, W, bi, C, true, reinterpret_cast<float4*>(zattn), gtid);
}

__global__ __launch_bounds__(256, 2) void out_proj_kernel(
    const float* __restrict__ Wo, const float* __restrict__ bo, float* __restrict__ out)
{
    gemm_tf32<false>(g_x, Wo, bo, out, false, nullptr, 0);
}

// ---------------- banded attention (tensor-core tf32) ------------------------
// Block: 64 query rows, key window 192 rows. 8 warps = 4 m-tiles x 2 halves.
#define KW  192
#define QST 68
#define KST 68
#define VST 72
#define PST 196
#define SMEM_ATTN ((64*QST + KW*KST + KW*VST + 64*PST) * 4)   // 175104 B

__global__ __launch_bounds__(256) void attn_kernel(float* __restrict__ attn_out)
{
    extern __shared__ float sm[];
    float* Qs = sm;                       // 64 x QST
    float* Ks = Qs + 64 * QST;            // 192 x KST
    float* Vs = Ks + KW * KST;            // 192 x VST
    float* Ps = Vs + KW * VST;            // 64 x PST
    __shared__ float pmax_[2][64];
    __shared__ float psum_[2][64];

    const int tid = threadIdx.x;
    const int bh  = blockIdx.y;
    const int i0  = blockIdx.x * 64;
    const int b   = bh >> 4, h = bh & 15;
    const int kg0 = i0 - HALF;

    const float* Qg = g_q + (size_t)bh * SS * DK;
    const float* Kg = g_k + (size_t)bh * SS * DK;
    const float* Vg = g_v + (size_t)bh * SS * DK;

    // ---- load Q (64x64) ----
    #pragma unroll
    for (int i = 0; i < 4; i++) {
        int f = tid + i * 256;
        int r = f >> 4, c = (f & 15) << 2;
        float4 v = *reinterpret_cast<const float4*>(&Qg[(size_t)(i0 + r) * DK + c]);
        *reinterpret_cast<float4*>(&Qs[r * QST + c]) = v;
    }
    // ---- load K,V (192x64), zero-fill out of range ----
    #pragma unroll
    for (int i = 0; i < 12; i++) {
        int f = tid + i * 256;
        int r = f >> 4, c = (f & 15) << 2;
        int gr = kg0 + r;
        float4 kv = make_float4(0.f, 0.f, 0.f, 0.f);
        float4 vv = kv;
        if (gr >= 0 && gr < SS) {
            kv = *reinterpret_cast<const float4*>(&Kg[(size_t)gr * DK + c]);
            vv = *reinterpret_cast<const float4*>(&Vg[(size_t)gr * DK + c]);
        }
        *reinterpret_cast<float4*>(&Ks[r * KST + c]) = kv;
        *reinterpret_cast<float4*>(&Vs[r * VST + c]) = vv;
    }
    __syncthreads();

    const int lane = tid & 31, warp = tid >> 5;
    const int g  = lane >> 2;          // 0..7
    const int kq = lane & 3;           // 0..3
    const int wm = warp >> 1;          // 0..3  -> 16-row m tile
    const int nh = warp & 1;           // 0..1  -> 96-key half
    const int m0w = wm * 16;
    const int n0w = nh * 96;

    // ---- scores: S[16 x 96] per warp via m16n8k8 tf32 mma ----
    float sacc[12][4];
    #pragma unroll
    for (int nt = 0; nt < 12; nt++)
        #pragma unroll
        for (int e = 0; e < 4; e++) sacc[nt][e] = 0.f;

    #pragma unroll
    for (int k0 = 0; k0 < DK; k0 += 8) {
        unsigned a0 = cvt_tf32(Qs[(m0w + g) * QST + k0 + kq]);
        unsigned a1 = cvt_tf32(Qs[(m0w + 8 + g) * QST + k0 + kq]);
        unsigned a2 = cvt_tf32(Qs[(m0w + g) * QST + k0 + kq + 4]);
        unsigned a3 = cvt_tf32(Qs[(m0w + 8 + g) * QST + k0 + kq + 4]);
        #pragma unroll
        for (int nt = 0; nt < 12; nt++) {
            unsigned b0 = cvt_tf32(Ks[(n0w + nt * 8 + g) * KST + k0 + kq]);
            unsigned b1 = cvt_tf32(Ks[(n0w + nt * 8 + g) * KST + k0 + kq + 4]);
            MMA_TF32(sacc[nt], a0, a1, a2, a3, b0, b1);
        }
    }

    // ---- mask + scale + row max (rows m0w+g and m0w+8+g) ----
    const int r0 = m0w + g, r1 = m0w + 8 + g;
    float mx0 = -INFINITY, mx1 = -INFINITY;
    #pragma unroll
    for (int nt = 0; nt < 12; nt++) {
        #pragma unroll
        for (int e = 0; e < 4; e++) {
            int col = n0w + nt * 8 + 2 * kq + (e & 1);
            int rl  = (e < 2) ? r0 : r1;
            int j   = kg0 + col;
            bool ok = (col >= rl) && (col <= rl + 128) && (j >= 0) && (j < SS);
            float vv = ok ? sacc[nt][e] * 0.125f : -INFINITY;
            sacc[nt][e] = vv;
            if (e < 2) mx0 = fmaxf(mx0, vv); else mx1 = fmaxf(mx1, vv);
        }
    }
    #pragma unroll
    for (int o = 1; o < 4; o <<= 1) {
        mx0 = fmaxf(mx0, __shfl_xor_sync(0xffffffffu, mx0, o));
        mx1 = fmaxf(mx1, __shfl_xor_sync(0xffffffffu, mx1, o));
    }
    if (kq == 0) { pmax_[nh][r0] = mx0; pmax_[nh][r1] = mx1; }
    __syncthreads();
    float M0 = fmaxf(pmax_[0][r0], pmax_[1][r0]);
    float M1 = fmaxf(pmax_[0][r1], pmax_[1][r1]);

    float s0 = 0.f, s1 = 0.f;
    #pragma unroll
    for (int nt = 0; nt < 12; nt++) {
        float e0 = __expf(sacc[nt][0] - M0);
        float e1 = __expf(sacc[nt][1] - M0);
        float e2 = __expf(sacc[nt][2] - M1);
        float e3 = __expf(sacc[nt][3] - M1);
        sacc[nt][0] = e0; sacc[nt][1] = e1; sacc[nt][2] = e2; sacc[nt][3] = e3;
        s0 += e0 + e1; s1 += e2 + e3;
    }
    #pragma unroll
    for (int o = 1; o < 4; o <<= 1) {
        s0 += __shfl_xor_sync(0xffffffffu, s0, o);
        s1 += __shfl_xor_sync(0xffffffffu, s1, o);
    }
    if (kq == 0) { psum_[nh][r0] = s0; psum_[nh][r1] = s1; }
    __syncthreads();
    float inv0 = 1.0f / (psum_[0][r0] + psum_[1][r0]);
    float inv1 = 1.0f / (psum_[0][r1] + psum_[1][r1]);

    // ---- store P to smem (row-major, zeros outside band) ----
    #pragma unroll
    for (int nt = 0; nt < 12; nt++) {
        int c = n0w + nt * 8 + 2 * kq;
        *reinterpret_cast<float2*>(&Ps[r0 * PST + c]) =
            make_float2(sacc[nt][0] * inv0, sacc[nt][1] * inv0);
        *reinterpret_cast<float2*>(&Ps[r1 * PST + c]) =
            make_float2(sacc[nt][2] * inv1, sacc[nt][3] * inv1);
    }
    __syncthreads();

    // ---- PV: X[16 x 32] per warp = P[16 x 192] @ V[192 x 64] (banded k) ----
    float pv[4][4];
    #pragma unroll
    for (int nt = 0; nt < 4; nt++)
        #pragma unroll
        for (int e = 0; e < 4; e++) pv[nt][e] = 0.f;

    const int n0v = nh * 32;
    // valid k-steps for this m-tile: cols [m0w, m0w+143] -> 18 of 24 steps
    #pragma unroll 1
    for (int kt = wm * 2; kt <= wm * 2 + 17; ++kt) {
        int k0 = kt * 8;
        unsigned a0 = cvt_tf32(Ps[r0 * PST + k0 + kq]);
        unsigned a1 = cvt_tf32(Ps[r1 * PST + k0 + kq]);
        unsigned a2 = cvt_tf32(Ps[r0 * PST + k0 + kq + 4]);
        unsigned a3 = cvt_tf32(Ps[r1 * PST + k0 + kq + 4]);
        #pragma unroll
        for (int nt = 0; nt < 4; nt++) {
            unsigned b0 = cvt_tf32(Vs[(k0 + kq) * VST + n0v + nt * 8 + g]);
            unsigned b1 = cvt_tf32(Vs[(k0 + kq + 4) * VST + n0v + nt * 8 + g]);
            MMA_TF32(pv[nt], a0, a1, a2, a3, b0, b1);
        }
    }

    // ---- write x tile to g_x [B,S,D] ----
    {
        float* xo0 = &g_x[((size_t)b * SS + (i0 + r0)) * DD + h * DK + n0v];
        float* xo1 = &g_x[((size_t)b * SS + (i0 + r1)) * DD + h * DK + n0v];
        #pragma unroll
        for (int nt = 0; nt < 4; nt++) {
            int c = nt * 8 + 2 * kq;
            *reinterpret_cast<float2*>(&xo0[c]) = make_float2(pv[nt][0], pv[nt][1]);
            *reinterpret_cast<float2*>(&xo1[c]) = make_float2(pv[nt][2], pv[nt][3]);
        }
    }

    // ---- write band of attn matrix (rest zero-filled by qkv_proj) ----
    for (int idx = tid; idx < 64 * 129; idx += 256) {
        int r = idx / 129;
        int t = idx - r * 129;
        int qg = i0 + r;
        int j  = qg - HALF + t;
        if (j >= 0 && j < SS)
            attn_out[((size_t)bh * SS + qg) * SS + j] = Ps[r * PST + r + t];
    }
}

// ---------------- launch -----------------------------------------------------
extern "C" void kernel_launch(void* const* d_in, const int* in_sizes, int n_in,
                              void* d_out, int out_size)
{
    const float* query = (const float*)d_in[0];
    const float* key   = (const float*)d_in[1];
    const float* value = (const float*)d_in[2];
    const float* Wq    = (const float*)d_in[3];
    const float* bq    = (const float*)d_in[4];
    const float* Wk    = (const float*)d_in[5];
    const float* bk    = (const float*)d_in[6];
    const float* Wv    = (const float*)d_in[7];
    const float* bv    = (const float*)d_in[8];
    const float* Wo    = (const float*)d_in[9];
    const float* bo    = (const float*)d_in[10];

    float* out  = (float*)d_out;
    float* attn = out + (size_t)BB * SS * DD;

    cudaFuncSetAttribute(qkv_proj_kernel, cudaFuncAttributeMaxDynamicSharedMemorySize, SMEM_GEMM);
    cudaFuncSetAttribute(out_proj_kernel, cudaFuncAttributeMaxDynamicSharedMemorySize, SMEM_GEMM);
    cudaFuncSetAttribute(attn_kernel,     cudaFuncAttributeMaxDynamicSharedMemorySize, SMEM_ATTN);

    // Q/K/V projections (TF32 tensor cores) + interleaved attn zero-fill
    qkv_proj_kernel<<<dim3(8, 32, 3), 256, SMEM_GEMM>>>(query, key, value,
                                                        Wq, Wk, Wv, bq, bk, bv, attn);

    // banded attention (tensor-core scores + PV; writes only the band)
    attn_kernel<<<dim3(SS / 64, BB * HH), 256, SMEM_ATTN>>>(attn);

    // output projection
    out_proj_kernel<<<dim3(8, 32), 256, SMEM_GEMM>>>(Wo, bo, out);
}

// round 5
// speedup vs baseline: 1.5995x; 1.0229x over previous
#include <cuda_runtime.h>
#include <cuda_bf16.h>
#include <math.h>

// Problem constants
#define BB   2
#define SS   2048
#define DD   1024
#define HH   16
#define DK   64
#define HALF 64

// ---------------- scratch (device globals; no runtime allocation) ----------
__device__ float g_q[BB*HH*SS*DK];   // [B,H,S,DK]
__device__ float g_k[BB*HH*SS*DK];
__device__ float g_v[BB*HH*SS*DK];
__device__ float g_x[BB*SS*DD];      // [B,S,D] attention output (tf32-rounded)
// tf32-rounded copies of inputs, and tf32-rounded TRANSPOSED weights [n][k]
__device__ float g_cq[BB*SS*DD];
__device__ float g_ck[BB*SS*DD];
__device__ float g_cv[BB*SS*DD];
__device__ float g_wq[DD*DD];
__device__ float g_wk[DD*DD];
__device__ float g_wv[DD*DD];
__device__ float g_wo[DD*DD];

// ---------------- helpers ----------------------------------------------------
__device__ __forceinline__ unsigned cvta_sh(const void* p) {
    return (unsigned)__cvta_generic_to_shared(p);
}
__device__ __forceinline__ unsigned cvt_tf32(float x) {
    unsigned r; asm("cvt.rna.tf32.f32 %0, %1;" : "=r"(r) : "f"(x)); return r;
}
#define CP_ASYNC16(saddr, gaddr) \
    asm volatile("cp.async.cg.shared.global [%0], [%1], 16;\n" :: "r"(saddr), "l"(gaddr))
#define CP_COMMIT() asm volatile("cp.async.commit_group;\n" ::)
#define CP_WAIT(N)  asm volatile("cp.async.wait_group %0;\n" :: "n"(N))

#define MMA_TF32(ac, a0,a1,a2,a3, b0,b1) \
    asm volatile( \
        "mma.sync.aligned.m16n8k8.row.col.f32.tf32.tf32.f32 " \
        "{%0,%1,%2,%3}, {%4,%5,%6,%7}, {%8,%9}, {%0,%1,%2,%3};" \
        : "+f"((ac)[0]), "+f"((ac)[1]), "+f"((ac)[2]), "+f"((ac)[3]) \
        : "r"(a0), "r"(a1), "r"(a2), "r"(a3), "r"(b0), "r"(b1))

#define LDSM4(r0,r1,r2,r3, addr) \
    asm volatile("ldmatrix.sync.aligned.m8n8.x4.shared.b16 {%0,%1,%2,%3}, [%4];" \
        : "=r"(r0), "=r"(r1), "=r"(r2), "=r"(r3) : "r"(addr))

// ---------------- prep: tf32-round inputs; transpose+round weights -----------
__global__ __launch_bounds__(256) void prep_cvt_kernel(
    const float* __restrict__ q, const float* __restrict__ k, const float* __restrict__ v)
{
    const float* src = (blockIdx.y == 0) ? q : (blockIdx.y == 1) ? k : v;
    float* dst = (blockIdx.y == 0) ? g_cq : (blockIdx.y == 1) ? g_ck : g_cv;
    size_t i = (size_t)blockIdx.x * 256 + threadIdx.x;   // float4 index, 1M per array
    float4 x = reinterpret_cast<const float4*>(src)[i];
    x.x = __uint_as_float(cvt_tf32(x.x));
    x.y = __uint_as_float(cvt_tf32(x.y));
    x.z = __uint_as_float(cvt_tf32(x.z));
    x.w = __uint_as_float(cvt_tf32(x.w));
    reinterpret_cast<float4*>(dst)[i] = x;
}

__global__ __launch_bounds__(256) void prep_transpose_kernel(
    const float* __restrict__ Wq, const float* __restrict__ Wk,
    const float* __restrict__ Wv, const float* __restrict__ Wo)
{
    __shared__ float tile[32][33];
    int z = blockIdx.z;
    const float* W = (z == 0) ? Wq : (z == 1) ? Wk : (z == 2) ? Wv : Wo;
    float* Wt      = (z == 0) ? g_wq : (z == 1) ? g_wk : (z == 2) ? g_wv : g_wo;
    int k0 = blockIdx.y * 32, n0 = blockIdx.x * 32;
    int tx = threadIdx.x & 31, ty = threadIdx.x >> 5;   // 32 x 8
    #pragma unroll
    for (int j = 0; j < 32; j += 8)
        tile[ty + j][tx] = W[(size_t)(k0 + ty + j) * DD + n0 + tx];
    __syncthreads();
    #pragma unroll
    for (int j = 0; j < 32; j += 8)
        Wt[(size_t)(n0 + ty + j) * DD + k0 + tx] =
            __uint_as_float(cvt_tf32(tile[tx][ty + j]));
}

// ---------------- TF32 tensor-core GEMM (ldmatrix fragments) -----------------
// A [M,K] k-major (tf32-rounded), Wt [N,K] k-major (tf32-rounded, transposed).
#define AS_STRIDE 36
#define BS_STRIDE 36
#define AS_STAGE  (128 * AS_STRIDE)
#define BS_STAGE  (128 * BS_STRIDE)
#define SMEM_GEMM ((2 * (AS_STAGE + BS_STAGE)) * 4)   // 73728 B

#define FILL_TOTAL4 ((size_t)BB * HH * SS * SS / 4)    // 33554432 float4
#define FILL_THREADS ((size_t)768 * 256)

__device__ __forceinline__ void gemm_load_stage(
    const float* __restrict__ A, const float* __restrict__ Wt,
    float* As, float* Bs, int stage, int k0, int m0, int n0, int tid)
{
    float* Ad = As + stage * AS_STAGE;
    float* Bd = Bs + stage * BS_STAGE;
    #pragma unroll
    for (int i = 0; i < 4; i++) {
        int f = tid + i * 256;          // 1024 chunks: 128 rows x 8 f4
        int r = f >> 3, c4 = f & 7;
        CP_ASYNC16(cvta_sh(&Ad[r * AS_STRIDE + c4 * 4]),
                   &A[(size_t)(m0 + r) * DD + k0 + c4 * 4]);
    }
    #pragma unroll
    for (int i = 0; i < 4; i++) {
        int f = tid + i * 256;          // 1024 chunks: 128 n-rows x 8 f4
        int r = f >> 3, c4 = f & 7;
        CP_ASYNC16(cvta_sh(&Bd[r * BS_STRIDE + c4 * 4]),
                   &Wt[(size_t)(n0 + r) * DD + k0 + c4 * 4]);
    }
    CP_COMMIT();
}

template <bool FILL>
__device__ __forceinline__ void gemm_tf32(const float* __restrict__ A,
                                          const float* __restrict__ Wt,
                                          const float* __restrict__ bias,
                                          float* __restrict__ C,
                                          bool permuted,
                                          float4* __restrict__ zdst,
                                          size_t gtid)
{
    extern __shared__ float sm[];
    float* As = sm;
    float* Bs = sm + 2 * AS_STAGE;

    const int tid  = threadIdx.x;
    const int lane = tid & 31;
    const int wid  = tid >> 5;
    const int wm   = wid >> 2;           // 0..1 -> 64-row tile
    const int wn   = wid & 3;            // 0..3 -> 32-col tile
    const int m0   = blockIdx.y * 128;
    const int n0   = blockIdx.x * 128;
    const int g    = lane >> 2;
    const int kq   = lane & 3;

    // ldmatrix lane base addresses (bytes, shared space)
    const int tIdx = lane >> 3;          // 0..3 (tile index within x4)
    const int tRow = lane & 7;
    const unsigned a_base = cvta_sh(As) +
        (((wm * 64 + tRow + (tIdx & 1) * 8) * AS_STRIDE + (tIdx >> 1) * 4) << 2);
    const unsigned b_base = cvta_sh(Bs) +
        (((wn * 32 + tRow + (tIdx >> 1) * 8) * BS_STRIDE + (tIdx & 1) * 4) << 2);

    float acc[4][4][4];
    #pragma unroll
    for (int i = 0; i < 4; i++)
        #pragma unroll
        for (int j = 0; j < 4; j++)
            #pragma unroll
            for (int e = 0; e < 4; e++) acc[i][j][e] = 0.f;

    gemm_load_stage(A, Wt, As, Bs, 0, 0, m0, n0, tid);

    const float4 z4 = make_float4(0.f, 0.f, 0.f, 0.f);

    #pragma unroll 1
    for (int t = 0; t < DD / 32; ++t) {
        if (t + 1 < DD / 32) {
            gemm_load_stage(A, Wt, As, Bs, (t + 1) & 1, (t + 1) * 32, m0, n0, tid);
            CP_WAIT(1);
        } else {
            CP_WAIT(0);
        }
        __syncthreads();

        // interleaved zero-fill: rides idle DRAM write BW under the mma loop
        if (FILL) {
            #pragma unroll
            for (int u = 0; u < 6; ++u) {
                size_t idx = (size_t)(t * 6 + u) * FILL_THREADS + gtid;
                if (idx < FILL_TOTAL4) zdst[idx] = z4;
            }
        }

        const unsigned aoff = a_base + (unsigned)((t & 1) * AS_STAGE * 4);
        const unsigned boff = b_base + (unsigned)((t & 1) * BS_STAGE * 4);

        #pragma unroll
        for (int kk = 0; kk < 4; ++kk) {
            unsigned a[4][4], b[4][2];
            #pragma unroll
            for (int mf = 0; mf < 4; ++mf)
                LDSM4(a[mf][0], a[mf][1], a[mf][2], a[mf][3],
                      aoff + (unsigned)(mf * 16 * AS_STRIDE * 4 + kk * 32));
            #pragma unroll
            for (int p = 0; p < 2; ++p)
                LDSM4(b[2*p][0], b[2*p][1], b[2*p+1][0], b[2*p+1][1],
                      boff + (unsigned)(p * 16 * BS_STRIDE * 4 + kk * 32));
            #pragma unroll
            for (int mf = 0; mf < 4; ++mf)
                #pragma unroll
                for (int nf = 0; nf < 4; ++nf)
                    MMA_TF32(acc[mf][nf], a[mf][0], a[mf][1], a[mf][2], a[mf][3],
                             b[nf][0], b[nf][1]);
        }
        __syncthreads();
    }

    // epilogue
    #pragma unroll
    for (int mf = 0; mf < 4; ++mf) {
        #pragma unroll
        for (int nf = 0; nf < 4; ++nf) {
            int m = m0 + wm * 64 + mf * 16 + g;
            int n = n0 + wn * 32 + nf * 8 + 2 * kq;
            float bn0 = bias[n], bn1 = bias[n + 1];
            #pragma unroll
            for (int half = 0; half < 2; ++half) {
                int mm = m + half * 8;
                float v0 = acc[mf][nf][half * 2 + 0] + bn0;
                float v1 = acc[mf][nf][half * 2 + 1] + bn1;
                int bb = mm >> 11, s = mm & 2047;
                if (permuted) {
                    int h = n >> 6, dk = n & 63;
                    float2* dst = reinterpret_cast<float2*>(
                        &g_q[0] + 0);   // placeholder avoided below
                    dst = reinterpret_cast<float2*>(
                        &C[((size_t)(bb * HH + h) * SS + s) * DK + dk]);
                    *dst = make_float2(v0, v1);
                } else {
                    float2* dst = reinterpret_cast<float2*>(&C[(size_t)mm * DD + n]);
                    *dst = make_float2(v0, v1);
                }
            }
        }
    }
}

__global__ __launch_bounds__(256, 2) void qkv_proj_kernel(
    const float* __restrict__ bq, const float* __restrict__ bk, const float* __restrict__ bv,
    float* __restrict__ zattn)
{
    int w = blockIdx.z;
    const float* A  = (w == 0) ? g_cq : (w == 1) ? g_ck : g_cv;
    const float* Wt = (w == 0) ? g_wq : (w == 1) ? g_wk : g_wv;
    const float* bi = (w == 0) ? bq : (w == 1) ? bk : bv;
    float* C        = (w == 0) ? g_q : (w == 1) ? g_k : g_v;
    const int bid   = blockIdx.x + blockIdx.y * 8 + blockIdx.z * 256;   // 0..767
    size_t gtid     = (size_t)bid * 256 + threadIdx.x;
    gemm_tf32<true>(A, Wt, bi, C, true, reinterpret_cast<float4*>(zattn), gtid);
}

__global__ __launch_bounds__(256, 2) void out_proj_kernel(
    const float* __restrict__ bo, float* __restrict__ out)
{
    gemm_tf32<false>(g_x, g_wo, bo, out, false, nullptr, 0);
}

// ---------------- banded attention (tensor-core tf32) ------------------------
#define KW  192
#define QST 68
#define KST 68
#define VST 72
#define PST 196
#define SMEM_ATTN ((64*QST + KW*KST + KW*VST + 64*PST) * 4)   // 175104 B

__global__ __launch_bounds__(256) void attn_kernel(float* __restrict__ attn_out)
{
    extern __shared__ float sm[];
    float* Qs = sm;                       // 64 x QST
    float* Ks = Qs + 64 * QST;            // 192 x KST
    float* Vs = Ks + KW * KST;            // 192 x VST
    float* Ps = Vs + KW * VST;            // 64 x PST
    __shared__ float pmax_[2][64];
    __shared__ float psum_[2][64];

    const int tid = threadIdx.x;
    const int bh  = blockIdx.y;
    const int i0  = blockIdx.x * 64;
    const int b   = bh >> 4, h = bh & 15;
    const int kg0 = i0 - HALF;

    const float* Qg = g_q + (size_t)bh * SS * DK;
    const float* Kg = g_k + (size_t)bh * SS * DK;
    const float* Vg = g_v + (size_t)bh * SS * DK;

    // ---- load Q (64x64) ----
    #pragma unroll
    for (int i = 0; i < 4; i++) {
        int f = tid + i * 256;
        int r = f >> 4, c = (f & 15) << 2;
        float4 v = *reinterpret_cast<const float4*>(&Qg[(size_t)(i0 + r) * DK + c]);
        *reinterpret_cast<float4*>(&Qs[r * QST + c]) = v;
    }
    // ---- load K,V (192x64), zero-fill out of range ----
    #pragma unroll
    for (int i = 0; i < 12; i++) {
        int f = tid + i * 256;
        int r = f >> 4, c = (f & 15) << 2;
        int gr = kg0 + r;
        float4 kv = make_float4(0.f, 0.f, 0.f, 0.f);
        float4 vv = kv;
        if (gr >= 0 && gr < SS) {
            kv = *reinterpret_cast<const float4*>(&Kg[(size_t)gr * DK + c]);
            vv = *reinterpret_cast<const float4*>(&Vg[(size_t)gr * DK + c]);
        }
        *reinterpret_cast<float4*>(&Ks[r * KST + c]) = kv;
        *reinterpret_cast<float4*>(&Vs[r * VST + c]) = vv;
    }
    __syncthreads();

    const int lane = tid & 31, warp = tid >> 5;
    const int g  = lane >> 2;
    const int kq = lane & 3;
    const int wm = warp >> 1;
    const int nh = warp & 1;
    const int m0w = wm * 16;
    const int n0w = nh * 96;

    // ---- scores: S[16 x 96] per warp ----
    float sacc[12][4];
    #pragma unroll
    for (int nt = 0; nt < 12; nt++)
        #pragma unroll
        for (int e = 0; e < 4; e++) sacc[nt][e] = 0.f;

    #pragma unroll
    for (int k0 = 0; k0 < DK; k0 += 8) {
        unsigned a0 = cvt_tf32(Qs[(m0w + g) * QST + k0 + kq]);
        unsigned a1 = cvt_tf32(Qs[(m0w + 8 + g) * QST + k0 + kq]);
        unsigned a2 = cvt_tf32(Qs[(m0w + g) * QST + k0 + kq + 4]);
        unsigned a3 = cvt_tf32(Qs[(m0w + 8 + g) * QST + k0 + kq + 4]);
        #pragma unroll
        for (int nt = 0; nt < 12; nt++) {
            unsigned b0 = cvt_tf32(Ks[(n0w + nt * 8 + g) * KST + k0 + kq]);
            unsigned b1 = cvt_tf32(Ks[(n0w + nt * 8 + g) * KST + k0 + kq + 4]);
            MMA_TF32(sacc[nt], a0, a1, a2, a3, b0, b1);
        }
    }

    // ---- mask + scale + row max ----
    const int r0 = m0w + g, r1 = m0w + 8 + g;
    float mx0 = -INFINITY, mx1 = -INFINITY;
    #pragma unroll
    for (int nt = 0; nt < 12; nt++) {
        #pragma unroll
        for (int e = 0; e < 4; e++) {
            int col = n0w + nt * 8 + 2 * kq + (e & 1);
            int rl  = (e < 2) ? r0 : r1;
            int j   = kg0 + col;
            bool ok = (col >= rl) && (col <= rl + 128) && (j >= 0) && (j < SS);
            float vv = ok ? sacc[nt][e] * 0.125f : -INFINITY;
            sacc[nt][e] = vv;
            if (e < 2) mx0 = fmaxf(mx0, vv); else mx1 = fmaxf(mx1, vv);
        }
    }
    #pragma unroll
    for (int o = 1; o < 4; o <<= 1) {
        mx0 = fmaxf(mx0, __shfl_xor_sync(0xffffffffu, mx0, o));
        mx1 = fmaxf(mx1, __shfl_xor_sync(0xffffffffu, mx1, o));
    }
    if (kq == 0) { pmax_[nh][r0] = mx0; pmax_[nh][r1] = mx1; }
    __syncthreads();
    float M0 = fmaxf(pmax_[0][r0], pmax_[1][r0]);
    float M1 = fmaxf(pmax_[0][r1], pmax_[1][r1]);

    float s0 = 0.f, s1 = 0.f;
    #pragma unroll
    for (int nt = 0; nt < 12; nt++) {
        float e0 = __expf(sacc[nt][0] - M0);
        float e1 = __expf(sacc[nt][1] - M0);
        float e2 = __expf(sacc[nt][2] - M1);
        float e3 = __expf(sacc[nt][3] - M1);
        sacc[nt][0] = e0; sacc[nt][1] = e1; sacc[nt][2] = e2; sacc[nt][3] = e3;
        s0 += e0 + e1; s1 += e2 + e3;
    }
    #pragma unroll
    for (int o = 1; o < 4; o <<= 1) {
        s0 += __shfl_xor_sync(0xffffffffu, s0, o);
        s1 += __shfl_xor_sync(0xffffffffu, s1, o);
    }
    if (kq == 0) { psum_[nh][r0] = s0; psum_[nh][r1] = s1; }
    __syncthreads();
    float inv0 = 1.0f / (psum_[0][r0] + psum_[1][r0]);
    float inv1 = 1.0f / (psum_[0][r1] + psum_[1][r1]);

    // ---- store P to smem ----
    #pragma unroll
    for (int nt = 0; nt < 12; nt++) {
        int c = n0w + nt * 8 + 2 * kq;
        *reinterpret_cast<float2*>(&Ps[r0 * PST + c]) =
            make_float2(sacc[nt][0] * inv0, sacc[nt][1] * inv0);
        *reinterpret_cast<float2*>(&Ps[r1 * PST + c]) =
            make_float2(sacc[nt][2] * inv1, sacc[nt][3] * inv1);
    }
    __syncthreads();

    // ---- PV: X[16 x 32] per warp (banded k) ----
    float pv[4][4];
    #pragma unroll
    for (int nt = 0; nt < 4; nt++)
        #pragma unroll
        for (int e = 0; e < 4; e++) pv[nt][e] = 0.f;

    const int n0v = nh * 32;
    #pragma unroll 1
    for (int kt = wm * 2; kt <= wm * 2 + 17; ++kt) {
        int k0 = kt * 8;
        unsigned a0 = cvt_tf32(Ps[r0 * PST + k0 + kq]);
        unsigned a1 = cvt_tf32(Ps[r1 * PST + k0 + kq]);
        unsigned a2 = cvt_tf32(Ps[r0 * PST + k0 + kq + 4]);
        unsigned a3 = cvt_tf32(Ps[r1 * PST + k0 + kq + 4]);
        #pragma unroll
        for (int nt = 0; nt < 4; nt++) {
            unsigned b0 = cvt_tf32(Vs[(k0 + kq) * VST + n0v + nt * 8 + g]);
            unsigned b1 = cvt_tf32(Vs[(k0 + kq + 4) * VST + n0v + nt * 8 + g]);
            MMA_TF32(pv[nt], a0, a1, a2, a3, b0, b1);
        }
    }

    // ---- write x tile to g_x (tf32-rounded for out_proj's ldmatrix path) ----
    {
        float* xo0 = &g_x[((size_t)b * SS + (i0 + r0)) * DD + h * DK + n0v];
        float* xo1 = &g_x[((size_t)b * SS + (i0 + r1)) * DD + h * DK + n0v];
        #pragma unroll
        for (int nt = 0; nt < 4; nt++) {
            int c = nt * 8 + 2 * kq;
            *reinterpret_cast<float2*>(&xo0[c]) = make_float2(
                __uint_as_float(cvt_tf32(pv[nt][0])), __uint_as_float(cvt_tf32(pv[nt][1])));
            *reinterpret_cast<float2*>(&xo1[c]) = make_float2(
                __uint_as_float(cvt_tf32(pv[nt][2])), __uint_as_float(cvt_tf32(pv[nt][3])));
        }
    }

    // ---- write band of attn matrix (rest zero-filled by qkv_proj) ----
    for (int idx = tid; idx < 64 * 129; idx += 256) {
        int r = idx / 129;
        int t = idx - r * 129;
        int qg = i0 + r;
        int j  = qg - HALF + t;
        if (j >= 0 && j < SS)
            attn_out[((size_t)bh * SS + qg) * SS + j] = Ps[r * PST + r + t];
    }
}

// ---------------- launch -----------------------------------------------------
extern "C" void kernel_launch(void* const* d_in, const int* in_sizes, int n_in,
                              void* d_out, int out_size)
{
    const float* query = (const float*)d_in[0];
    const float* key   = (const float*)d_in[1];
    const float* value = (const float*)d_in[2];
    const float* Wq    = (const float*)d_in[3];
    const float* bq    = (const float*)d_in[4];
    const float* Wk    = (const float*)d_in[5];
    const float* bk    = (const float*)d_in[6];
    const float* Wv    = (const float*)d_in[7];
    const float* bv    = (const float*)d_in[8];
    const float* Wo    = (const float*)d_in[9];
    const float* bo    = (const float*)d_in[10];

    float* out  = (float*)d_out;
    float* attn = out + (size_t)BB * SS * DD;

    cudaFuncSetAttribute(qkv_proj_kernel, cudaFuncAttributeMaxDynamicSharedMemorySize, SMEM_GEMM);
    cudaFuncSetAttribute(out_proj_kernel, cudaFuncAttributeMaxDynamicSharedMemorySize, SMEM_GEMM);
    cudaFuncSetAttribute(attn_kernel,     cudaFuncAttributeMaxDynamicSharedMemorySize, SMEM_ATTN);

    // prep: tf32-round inputs, transpose+round weights
    prep_cvt_kernel<<<dim3(4096, 3), 256>>>(query, key, value);
    prep_transpose_kernel<<<dim3(32, 32, 4), 256>>>(Wq, Wk, Wv, Wo);

    // Q/K/V projections (ldmatrix + TF32 mma) + interleaved attn zero-fill
    qkv_proj_kernel<<<dim3(8, 32, 3), 256, SMEM_GEMM>>>(bq, bk, bv, attn);

    // banded attention
    attn_kernel<<<dim3(SS / 64, BB * HH), 256, SMEM_ATTN>>>(attn);

    // output projection
    out_proj_kernel<<<dim3(8, 32), 256, SMEM_GEMM>>>(bo, out);
}